// round 7
// baseline (speedup 1.0000x reference)
#include <cuda_runtime.h>
#include <cuda_bf16.h>
#include <cstdint>

// Per-segment vocab histogram, f32, 16 slots (64B)/segment. Slots 14,15 never
// written. Zero-initialized at module load; the mma kernel re-zeros rows it
// consumes, so every graph replay starts from zeros.
#define MAX_T_ (1 << 17)
__device__ float g_hist[MAX_T_ * 16];

// pack two f32 -> bf16x2 ('lo' lands in the low 16 bits)
#define PACK_BF16X2(res, lo, hi) \
    asm("cvt.rn.bf16x2.f32 %0, %1, %2;" : "=r"(res) : "f"(hi), "f"(lo))

static __device__ __forceinline__ void mma_bf16(
    float& d0, float& d1, float& d2, float& d3,
    uint32_t a0, uint32_t a1, uint32_t a2, uint32_t a3,
    uint32_t b0, uint32_t b1)
{
    asm volatile(
        "mma.sync.aligned.m16n8k16.row.col.f32.bf16.bf16.f32 "
        "{%0,%1,%2,%3}, {%4,%5,%6,%7}, {%8,%9}, {%0,%1,%2,%3};"
        : "+f"(d0), "+f"(d1), "+f"(d2), "+f"(d3)
        : "r"(a0), "r"(a1), "r"(a2), "r"(a3), "r"(b0), "r"(b1));
}

// ---------------------------------------------------------------------------
// Kernel 1: histogram, 4 chars/thread via int4 loads, f32 RED.ADD.
__global__ void hist_kernel(const int4* __restrict__ seg4,
                            const int4* __restrict__ cidx4,
                            const int* __restrict__ seg,
                            const int* __restrict__ cidx,
                            int nq, int N) {
    int i = blockIdx.x * blockDim.x + threadIdx.x;
    if (i < nq) {
        int4 s = seg4[i];
        int4 c = cidx4[i];
        atomicAdd(&g_hist[(s.x << 4) + c.x], 1.0f);
        atomicAdd(&g_hist[(s.y << 4) + c.y], 1.0f);
        atomicAdd(&g_hist[(s.z << 4) + c.z], 1.0f);
        atomicAdd(&g_hist[(s.w << 4) + c.w], 1.0f);
    } else if (i == nq) {
        for (int j = nq * 4; j < N; ++j)
            atomicAdd(&g_hist[(seg[j] << 4) + cidx[j]], 1.0f);
    }
}

// ---------------------------------------------------------------------------
// Kernel 2: warp-pair bf16 HMMA GEMM.
//   out[t][n] = (sum_v hist[t][v] * emb[v][n]) / max(len_t, 1)
// Warps work in pairs over the same segments: even warp -> cols 0..63,
// odd warp -> cols 64..127. B (emb hi+lo bf16 split) is 32 regs per warp.
// Hist loads are software-pipelined one m-tile ahead; hi/lo MMAs use
// independent accumulators. Even warp re-zeros consumed hist rows after a
// pair-scoped named barrier (so the odd warp's loads are complete).
// WTILES kept small so the grid is large enough to fill 148 SMs.
#define WTILES 2   // m-tiles of 16 segments per warp-pair

__global__ void __launch_bounds__(256, 3)
mma_kernel(const float* __restrict__ emb, float* __restrict__ out, int T) {
    const int lane = threadIdx.x & 31;
    const int q    = lane & 3;          // threadID_in_group
    const int g    = lane >> 2;         // groupID
    const int half = (threadIdx.x >> 5) & 1;          // 0: cols 0-63, 1: 64-127
    const int pair_in_blk = threadIdx.x >> 6;         // 0..3
    const int pair = blockIdx.x * 4 + pair_in_blk;
    const int t_base = pair * (WTILES * 16);
    if (t_base >= T) return;
    const int bar_id = 8 + pair_in_blk;               // named barrier per pair

    // ---- B fragments for this half: j covers cols 64*half + 8j .. +7 ----
    uint32_t bhi[8][2], blo[8][2];
    const int k0 = 2 * q, k1 = 2 * q + 1, k2 = 2 * q + 8, k3 = 2 * q + 9;
#pragma unroll
    for (int j = 0; j < 8; ++j) {
        const int n = 64 * half + 8 * j + g;
        float e0 = (k0 < 14) ? emb[k0 * 128 + n] : 0.f;
        float e1 = (k1 < 14) ? emb[k1 * 128 + n] : 0.f;
        float e2 = (k2 < 14) ? emb[k2 * 128 + n] : 0.f;
        float e3 = (k3 < 14) ? emb[k3 * 128 + n] : 0.f;
        uint32_t h0, h1;
        PACK_BF16X2(h0, e0, e1);
        PACK_BF16X2(h1, e2, e3);
        bhi[j][0] = h0; bhi[j][1] = h1;
        float r0 = e0 - __uint_as_float(h0 << 16);
        float r1 = e1 - __uint_as_float(h0 & 0xffff0000u);
        float r2 = e2 - __uint_as_float(h1 << 16);
        float r3 = e3 - __uint_as_float(h1 & 0xffff0000u);
        uint32_t l0, l1;
        PACK_BF16X2(l0, r0, r1);
        PACK_BF16X2(l1, r2, r3);
        blo[j][0] = l0; blo[j][1] = l1;
    }

    const float2* hist2 = reinterpret_cast<const float2*>(g_hist);
    const float4  zero4 = make_float4(0.f, 0.f, 0.f, 0.f);
    const float2  zero2 = make_float2(0.f, 0.f);

    // ---- prologue: load m-tile 0 ----
    int t0 = t_base;
    float2 p00 = zero2, p01 = zero2, p10 = zero2, p11 = zero2;
    {
        const int tr0 = t0 + g, tr1 = t0 + g + 8;
        if (tr0 < T) { p00 = hist2[(size_t)tr0 * 8 + q];
                       p01 = hist2[(size_t)tr0 * 8 + q + 4]; }
        if (tr1 < T) { p10 = hist2[(size_t)tr1 * 8 + q];
                       p11 = hist2[(size_t)tr1 * 8 + q + 4]; }
    }

#pragma unroll 1
    for (int mt = 0; mt < WTILES; ++mt) {
        const int tr0 = t0 + g;
        const int tr1 = t0 + g + 8;
        const bool ok0 = (tr0 < T);
        const bool ok1 = (tr1 < T);

        // ---- pack A fragments + segment lengths (consumes the loads) ----
        uint32_t a0, a1, a2, a3;
        PACK_BF16X2(a0, p00.x, p00.y);
        PACK_BF16X2(a1, p10.x, p10.y);
        PACK_BF16X2(a2, p01.x, p01.y);
        PACK_BF16X2(a3, p11.x, p11.y);

        float len0 = (p00.x + p00.y) + (p01.x + p01.y);
        float len1 = (p10.x + p10.y) + (p11.x + p11.y);
        len0 += __shfl_xor_sync(0xffffffffu, len0, 1);
        len1 += __shfl_xor_sync(0xffffffffu, len1, 1);
        len0 += __shfl_xor_sync(0xffffffffu, len0, 2);
        len1 += __shfl_xor_sync(0xffffffffu, len1, 2);
        const float s0 = __fdividef(1.0f, fmaxf(len0, 1.0f));
        const float s1 = __fdividef(1.0f, fmaxf(len1, 1.0f));

        // ---- pair barrier: both warps' loads of these rows are complete ----
        asm volatile("bar.sync %0, %1;" :: "r"(bar_id), "r"(64) : "memory");

        // ---- even warp clears the consumed rows ----
        if (half == 0) {
            const int zr = t0 + (lane >> 1);
            if (zr < T) {
                float4* hz = reinterpret_cast<float4*>(
                    g_hist + (size_t)zr * 16 + (lane & 1) * 8);
                hz[0] = zero4; hz[1] = zero4;
            }
        }

        // ---- prefetch next m-tile's hist rows ----
        const int t0n = t0 + 16;
        if (mt + 1 < WTILES) {
            const int nr0 = t0n + g, nr1 = t0n + g + 8;
            p00 = zero2; p01 = zero2; p10 = zero2; p11 = zero2;
            if (nr0 < T) { p00 = hist2[(size_t)nr0 * 8 + q];
                           p01 = hist2[(size_t)nr0 * 8 + q + 4]; }
            if (nr1 < T) { p10 = hist2[(size_t)nr1 * 8 + q];
                           p11 = hist2[(size_t)nr1 * 8 + q + 4]; }
        }

        // ---- 8 n-tiles: independent hi/lo MMAs + scaled stores ----
        float* po0 = out + (size_t)tr0 * 128 + 64 * half + 2 * q;
        float* po1 = out + (size_t)tr1 * 128 + 64 * half + 2 * q;
#pragma unroll
        for (int j = 0; j < 8; ++j) {
            float h0 = 0.f, h1 = 0.f, h2 = 0.f, h3 = 0.f;
            float l0 = 0.f, l1 = 0.f, l2 = 0.f, l3 = 0.f;
            mma_bf16(h0, h1, h2, h3, a0, a1, a2, a3, bhi[j][0], bhi[j][1]);
            mma_bf16(l0, l1, l2, l3, a0, a1, a2, a3, blo[j][0], blo[j][1]);
            if (ok0) *reinterpret_cast<float2*>(po0 + 8 * j) =
                         make_float2((h0 + l0) * s0, (h1 + l1) * s0);
            if (ok1) *reinterpret_cast<float2*>(po1 + 8 * j) =
                         make_float2((h2 + l2) * s1, (h3 + l3) * s1);
        }

        t0 = t0n;
    }
}

// ---------------------------------------------------------------------------
extern "C" void kernel_launch(void* const* d_in, const int* in_sizes, int n_in,
                              void* d_out, int out_size) {
    const float* char_emb     = (const float*)d_in[0];
    const int*   char_indices = (const int*)d_in[1];
    const int*   segment_ids  = (const int*)d_in[2];
    float*       out          = (float*)d_out;

    int N = in_sizes[1];          // total chars
    int T = out_size / 128;       // segments (d_model = 128)

    {   // histogram
        int nq = N >> 2;
        int threads = 256;
        int work = nq + 1;
        hist_kernel<<<(work + threads - 1) / threads, threads>>>(
            (const int4*)segment_ids, (const int4*)char_indices,
            segment_ids, char_indices, nq, N);
    }
    {   // HMMA GEMM: 8 warps = 4 warp-pairs per block, 32 segs per pair
        int segs_per_block = 4 * WTILES * 16;   // 128
        int blocks = (T + segs_per_block - 1) / segs_per_block;
        mma_kernel<<<blocks, 256>>>(char_emb, out, T);
    }
}

// round 10
// speedup vs baseline: 1.0918x; 1.0918x over previous
#include <cuda_runtime.h>
#include <cuda_bf16.h>
#include <cstdint>

// Per-segment vocab histogram, f32, 16 slots (64B)/segment. Slots 14,15 never
// written. Zero-initialized at module load; the mma kernel re-zeros rows it
// consumes, so every graph replay starts from zeros.
#define MAX_T_ (1 << 17)
__device__ float g_hist[MAX_T_ * 16];

// Precomputed B fragments (emb as bf16 hi + bf16 residual lo), written by
// hist_kernel block 0 each replay (deterministic). Layout [half][j][lane]
// so an mma warp loads them with coalesced LDG.64.
__device__ uint2 g_bHI[2][8][32];
__device__ uint2 g_bLO[2][8][32];

// pack two f32 -> bf16x2 ('lo' lands in the low 16 bits)
#define PACK_BF16X2(res, lo, hi) \
    asm("cvt.rn.bf16x2.f32 %0, %1, %2;" : "=r"(res) : "f"(hi), "f"(lo))

static __device__ __forceinline__ void mma_bf16(
    float& d0, float& d1, float& d2, float& d3,
    uint32_t a0, uint32_t a1, uint32_t a2, uint32_t a3,
    uint32_t b0, uint32_t b1)
{
    asm volatile(
        "mma.sync.aligned.m16n8k16.row.col.f32.bf16.bf16.f32 "
        "{%0,%1,%2,%3}, {%4,%5,%6,%7}, {%8,%9}, {%0,%1,%2,%3};"
        : "+f"(d0), "+f"(d1), "+f"(d2), "+f"(d3)
        : "r"(a0), "r"(a1), "r"(a2), "r"(a3), "r"(b0), "r"(b1));
}

// ---------------------------------------------------------------------------
// Kernel 1: histogram (4 chars/thread, f32 RED.ADD) + B-fragment precompute
// (block 0, first 64 threads).
__global__ void hist_kernel(const int4* __restrict__ seg4,
                            const int4* __restrict__ cidx4,
                            const int* __restrict__ seg,
                            const int* __restrict__ cidx,
                            const float* __restrict__ emb,
                            int nq, int N) {
    // ---- B-fragment precompute (runs alongside this block's hist work) ----
    if (blockIdx.x == 0 && threadIdx.x < 64) {
        const int half = threadIdx.x >> 5;
        const int lane = threadIdx.x & 31;
        const int q = lane & 3, g = lane >> 2;
        const int k0 = 2 * q, k1 = 2 * q + 1, k2 = 2 * q + 8, k3 = 2 * q + 9;
#pragma unroll
        for (int j = 0; j < 8; ++j) {
            const int n = 64 * half + 8 * j + g;
            float e0 = (k0 < 14) ? emb[k0 * 128 + n] : 0.f;
            float e1 = (k1 < 14) ? emb[k1 * 128 + n] : 0.f;
            float e2 = (k2 < 14) ? emb[k2 * 128 + n] : 0.f;
            float e3 = (k3 < 14) ? emb[k3 * 128 + n] : 0.f;
            uint32_t h0, h1;
            PACK_BF16X2(h0, e0, e1);
            PACK_BF16X2(h1, e2, e3);
            float r0 = e0 - __uint_as_float(h0 << 16);
            float r1 = e1 - __uint_as_float(h0 & 0xffff0000u);
            float r2 = e2 - __uint_as_float(h1 << 16);
            float r3 = e3 - __uint_as_float(h1 & 0xffff0000u);
            uint32_t l0, l1;
            PACK_BF16X2(l0, r0, r1);
            PACK_BF16X2(l1, r2, r3);
            g_bHI[half][j][lane] = make_uint2(h0, h1);
            g_bLO[half][j][lane] = make_uint2(l0, l1);
        }
    }

    int i = blockIdx.x * blockDim.x + threadIdx.x;
    if (i < nq) {
        int4 s = seg4[i];
        int4 c = cidx4[i];
        atomicAdd(&g_hist[(s.x << 4) + c.x], 1.0f);
        atomicAdd(&g_hist[(s.y << 4) + c.y], 1.0f);
        atomicAdd(&g_hist[(s.z << 4) + c.z], 1.0f);
        atomicAdd(&g_hist[(s.w << 4) + c.w], 1.0f);
    } else if (i == nq) {
        for (int j = nq * 4; j < N; ++j)
            atomicAdd(&g_hist[(seg[j] << 4) + cidx[j]], 1.0f);
    }
}

// ---------------------------------------------------------------------------
// Kernel 2: warp-pair bf16 HMMA GEMM.
//   out[t][n] = (sum_v hist[t][v] * emb[v][n]) / max(len_t, 1)
// Even warp -> cols 0..63, odd warp -> cols 64..127 of the same segments.
// B fragments loaded from the precomputed buffer (16 coalesced LDG.64).
// Hist loads software-pipelined one m-tile ahead; hi/lo MMAs independent.
// Even warp re-zeros consumed hist rows after a pair-scoped named barrier.
#define WTILES 2   // m-tiles of 16 segments per warp-pair

__global__ void __launch_bounds__(256, 3)
mma_kernel(float* __restrict__ out, int T) {
    const int lane = threadIdx.x & 31;
    const int q    = lane & 3;          // threadID_in_group
    const int g    = lane >> 2;         // groupID
    const int half = (threadIdx.x >> 5) & 1;          // 0: cols 0-63, 1: 64-127
    const int pair_in_blk = threadIdx.x >> 6;         // 0..3
    const int pair = blockIdx.x * 4 + pair_in_blk;
    const int t_base = pair * (WTILES * 16);
    if (t_base >= T) return;
    const int bar_id = 8 + pair_in_blk;               // named barrier per pair

    // ---- B fragments: 16 coalesced LDG.64 from the precomputed buffer ----
    uint32_t bhi[8][2], blo[8][2];
#pragma unroll
    for (int j = 0; j < 8; ++j) {
        uint2 h = g_bHI[half][j][lane];
        uint2 l = g_bLO[half][j][lane];
        bhi[j][0] = h.x; bhi[j][1] = h.y;
        blo[j][0] = l.x; blo[j][1] = l.y;
    }

    const float2* hist2 = reinterpret_cast<const float2*>(g_hist);
    const float4  zero4 = make_float4(0.f, 0.f, 0.f, 0.f);
    const float2  zero2 = make_float2(0.f, 0.f);

    // ---- prologue: load m-tile 0 ----
    int t0 = t_base;
    float2 p00 = zero2, p01 = zero2, p10 = zero2, p11 = zero2;
    {
        const int tr0 = t0 + g, tr1 = t0 + g + 8;
        if (tr0 < T) { p00 = hist2[(size_t)tr0 * 8 + q];
                       p01 = hist2[(size_t)tr0 * 8 + q + 4]; }
        if (tr1 < T) { p10 = hist2[(size_t)tr1 * 8 + q];
                       p11 = hist2[(size_t)tr1 * 8 + q + 4]; }
    }

#pragma unroll 1
    for (int mt = 0; mt < WTILES; ++mt) {
        const int tr0 = t0 + g;
        const int tr1 = t0 + g + 8;
        const bool ok0 = (tr0 < T);
        const bool ok1 = (tr1 < T);

        // ---- pack A fragments + segment lengths (consumes the loads) ----
        uint32_t a0, a1, a2, a3;
        PACK_BF16X2(a0, p00.x, p00.y);
        PACK_BF16X2(a1, p10.x, p10.y);
        PACK_BF16X2(a2, p01.x, p01.y);
        PACK_BF16X2(a3, p11.x, p11.y);

        float len0 = (p00.x + p00.y) + (p01.x + p01.y);
        float len1 = (p10.x + p10.y) + (p11.x + p11.y);
        len0 += __shfl_xor_sync(0xffffffffu, len0, 1);
        len1 += __shfl_xor_sync(0xffffffffu, len1, 1);
        len0 += __shfl_xor_sync(0xffffffffu, len0, 2);
        len1 += __shfl_xor_sync(0xffffffffu, len1, 2);
        const float s0 = __fdividef(1.0f, fmaxf(len0, 1.0f));
        const float s1 = __fdividef(1.0f, fmaxf(len1, 1.0f));

        // ---- pair barrier: both warps' loads of these rows are complete ----
        asm volatile("bar.sync %0, %1;" :: "r"(bar_id), "r"(64) : "memory");

        // ---- even warp clears the consumed rows ----
        if (half == 0) {
            const int zr = t0 + (lane >> 1);
            if (zr < T) {
                float4* hz = reinterpret_cast<float4*>(
                    g_hist + (size_t)zr * 16 + (lane & 1) * 8);
                hz[0] = zero4; hz[1] = zero4;
            }
        }

        // ---- prefetch next m-tile's hist rows ----
        const int t0n = t0 + 16;
        if (mt + 1 < WTILES) {
            const int nr0 = t0n + g, nr1 = t0n + g + 8;
            p00 = zero2; p01 = zero2; p10 = zero2; p11 = zero2;
            if (nr0 < T) { p00 = hist2[(size_t)nr0 * 8 + q];
                           p01 = hist2[(size_t)nr0 * 8 + q + 4]; }
            if (nr1 < T) { p10 = hist2[(size_t)nr1 * 8 + q];
                           p11 = hist2[(size_t)nr1 * 8 + q + 4]; }
        }

        // ---- 8 n-tiles: independent hi/lo MMAs + scaled stores ----
        float* po0 = out + (size_t)tr0 * 128 + 64 * half + 2 * q;
        float* po1 = out + (size_t)tr1 * 128 + 64 * half + 2 * q;
#pragma unroll
        for (int j = 0; j < 8; ++j) {
            float h0 = 0.f, h1 = 0.f, h2 = 0.f, h3 = 0.f;
            float l0 = 0.f, l1 = 0.f, l2 = 0.f, l3 = 0.f;
            mma_bf16(h0, h1, h2, h3, a0, a1, a2, a3, bhi[j][0], bhi[j][1]);
            mma_bf16(l0, l1, l2, l3, a0, a1, a2, a3, blo[j][0], blo[j][1]);
            if (ok0) *reinterpret_cast<float2*>(po0 + 8 * j) =
                         make_float2((h0 + l0) * s0, (h1 + l1) * s0);
            if (ok1) *reinterpret_cast<float2*>(po1 + 8 * j) =
                         make_float2((h2 + l2) * s1, (h3 + l3) * s1);
        }

        t0 = t0n;
    }
}

// ---------------------------------------------------------------------------
extern "C" void kernel_launch(void* const* d_in, const int* in_sizes, int n_in,
                              void* d_out, int out_size) {
    const float* char_emb     = (const float*)d_in[0];
    const int*   char_indices = (const int*)d_in[1];
    const int*   segment_ids  = (const int*)d_in[2];
    float*       out          = (float*)d_out;

    int N = in_sizes[1];          // total chars
    int T = out_size / 128;       // segments (d_model = 128)

    {   // histogram + B-fragment precompute
        int nq = N >> 2;
        int threads = 256;
        int work = nq + 1;
        hist_kernel<<<(work + threads - 1) / threads, threads>>>(
            (const int4*)segment_ids, (const int4*)char_indices,
            segment_ids, char_indices, char_emb, nq, N);
    }
    {   // HMMA GEMM: 8 warps = 4 warp-pairs per block, 32 segs per pair
        int segs_per_block = 4 * WTILES * 16;   // 128
        int blocks = (T + segs_per_block - 1) / segs_per_block;
        mma_kernel<<<blocks, 256>>>(out, T);
    }
}

// round 11
// speedup vs baseline: 1.3333x; 1.2212x over previous
#include <cuda_runtime.h>
#include <cuda_bf16.h>
#include <cstdint>

// Per-segment vocab histogram: 14 x 8-bit counts packed in two u64 per
// segment (.x = vocab 0-7, .y = vocab 8-13; top 2 bytes of .y always 0).
// Zero-initialized at module load; the mma kernel re-zeros rows it consumes,
// so every graph replay starts from zeros. Counts are exact (max seg len
// ~45 << 255, so 8-bit fields never carry).
#define MAX_T_ (1 << 17)
__device__ ulonglong2 g_hist2[MAX_T_];

// Precomputed B fragments (emb as bf16 hi + bf16 residual lo), written by
// hist_kernel block 0 each replay. Columns are PERMUTED so that tile-pair
// (2u, 2u+1) gives lane (g,q) output columns 16u+4q .. 16u+4q+3 -> STG.128.
__device__ uint2 g_bHI[2][8][32];
__device__ uint2 g_bLO[2][8][32];

// pack two f32 -> bf16x2 ('lo' lands in the low 16 bits)
#define PACK_BF16X2(res, lo, hi) \
    asm("cvt.rn.bf16x2.f32 %0, %1, %2;" : "=r"(res) : "f"(hi), "f"(lo))

#define DP4A_ACC(res, a, acc) \
    asm("dp4a.u32.u32 %0, %1, %2, %3;" : "=r"(res) : "r"(a), "r"(0x01010101u), "r"(acc))

static __device__ __forceinline__ void mma_bf16(
    float& d0, float& d1, float& d2, float& d3,
    uint32_t a0, uint32_t a1, uint32_t a2, uint32_t a3,
    uint32_t b0, uint32_t b1)
{
    asm volatile(
        "mma.sync.aligned.m16n8k16.row.col.f32.bf16.bf16.f32 "
        "{%0,%1,%2,%3}, {%4,%5,%6,%7}, {%8,%9}, {%0,%1,%2,%3};"
        : "+f"(d0), "+f"(d1), "+f"(d2), "+f"(d3)
        : "r"(a0), "r"(a1), "r"(a2), "r"(a3), "r"(b0), "r"(b1));
}

// ---------------------------------------------------------------------------
// Kernel 1: histogram with packed-u64 run aggregation (8 chars/thread) +
// B-fragment precompute (block 0, first 64 threads).
__global__ void hist_kernel(const int4* __restrict__ seg4,
                            const int4* __restrict__ cidx4,
                            const int* __restrict__ seg,
                            const int* __restrict__ cidx,
                            const float* __restrict__ emb,
                            int nq8, int N) {
    // ---- B-fragment precompute (permuted columns for STG.128 stores) ----
    if (blockIdx.x == 0 && threadIdx.x < 64) {
        const int half = threadIdx.x >> 5;
        const int lane = threadIdx.x & 31;
        const int q = lane & 3, g = lane >> 2;
        const int k0 = 2 * q, k1 = 2 * q + 1, k2 = 2 * q + 8, k3 = 2 * q + 9;
#pragma unroll
        for (int j = 0; j < 8; ++j) {
            const int u = j >> 1, odd = j & 1;
            // column permutation: even g -> 16u+2g+2*odd ; odd g -> 16u+2g-1+2*odd
            const int nin = 16 * u + 2 * g + 2 * odd - (g & 1);
            const int n = 64 * half + nin;
            float e0 = (k0 < 14) ? emb[k0 * 128 + n] : 0.f;
            float e1 = (k1 < 14) ? emb[k1 * 128 + n] : 0.f;
            float e2 = (k2 < 14) ? emb[k2 * 128 + n] : 0.f;
            float e3 = (k3 < 14) ? emb[k3 * 128 + n] : 0.f;
            uint32_t h0, h1;
            PACK_BF16X2(h0, e0, e1);
            PACK_BF16X2(h1, e2, e3);
            float r0 = e0 - __uint_as_float(h0 << 16);
            float r1 = e1 - __uint_as_float(h0 & 0xffff0000u);
            float r2 = e2 - __uint_as_float(h1 << 16);
            float r3 = e3 - __uint_as_float(h1 & 0xffff0000u);
            uint32_t l0, l1;
            PACK_BF16X2(l0, r0, r1);
            PACK_BF16X2(l1, r2, r3);
            g_bHI[half][j][lane] = make_uint2(h0, h1);
            g_bLO[half][j][lane] = make_uint2(l0, l1);
        }
    }

    const int i = blockIdx.x * blockDim.x + threadIdx.x;
    if (i < nq8) {
        int4 sa = seg4[2 * i], sb = seg4[2 * i + 1];
        int4 ca = cidx4[2 * i], cb = cidx4[2 * i + 1];
        int s_[8] = { sa.x, sa.y, sa.z, sa.w, sb.x, sb.y, sb.z, sb.w };
        int c_[8] = { ca.x, ca.y, ca.z, ca.w, cb.x, cb.y, cb.z, cb.w };

        unsigned long long lo = 0ull, hi = 0ull;
        int cur = s_[0];
#pragma unroll
        for (int k = 0; k < 8; ++k) {
            if (s_[k] != cur) {               // flush completed run
                atomicAdd(&g_hist2[cur].x, lo);
                if (hi) atomicAdd(&g_hist2[cur].y, hi);
                lo = 0ull; hi = 0ull; cur = s_[k];
            }
            unsigned long long one = 1ull << ((c_[k] & 7) * 8);
            if (c_[k] < 8) lo += one; else hi += one;
        }
        atomicAdd(&g_hist2[cur].x, lo);
        if (hi) atomicAdd(&g_hist2[cur].y, hi);
    } else if (i == nq8) {                    // scalar tail
        for (int j = nq8 * 8; j < N; ++j) {
            int t = seg[j], c = cidx[j];
            unsigned long long one = 1ull << ((c & 7) * 8);
            if (c < 8) atomicAdd(&g_hist2[t].x, one);
            else       atomicAdd(&g_hist2[t].y, one);
        }
    }
}

// ---------------------------------------------------------------------------
// Build A-fragment halves + segment length from one packed hist row.
static __device__ __forceinline__ void row_frag(
    ulonglong2 r, int q, uint32_t& aL, uint32_t& aH, float& lenf)
{
    const unsigned sh = (unsigned)q * 16u;
    float f0 = (float)((uint32_t)(r.x >> sh) & 0xffu);
    float f1 = (float)((uint32_t)(r.x >> (sh + 8u)) & 0xffu);
    float f2 = (float)((uint32_t)(r.y >> sh) & 0xffu);
    float f3 = (float)((uint32_t)(r.y >> (sh + 8u)) & 0xffu);
    PACK_BF16X2(aL, f0, f1);
    PACK_BF16X2(aH, f2, f3);
    uint32_t w0 = (uint32_t)r.x, w1 = (uint32_t)(r.x >> 32);
    uint32_t w2 = (uint32_t)r.y, w3 = (uint32_t)(r.y >> 32);
    uint32_t len;
    DP4A_ACC(len, w0, 0u);
    DP4A_ACC(len, w1, len);
    DP4A_ACC(len, w2, len);
    DP4A_ACC(len, w3, len);
    lenf = (float)len;
}

// ---------------------------------------------------------------------------
// Kernel 2: warp-pair bf16 HMMA GEMM with STG.128 epilogue.
// Even warp -> cols 0..63, odd warp -> cols 64..127 of the same segments.
// A built from packed u8 hist rows (1 LDG.128/row, dp4a len, no shfl).
// Tile-pairs (2u,2u+1) store one float4 per row per u (column-permuted B).
#define WTILES 2   // m-tiles of 16 segments per warp-pair

__global__ void __launch_bounds__(256, 3)
mma_kernel(float* __restrict__ out, int T) {
    const int lane = threadIdx.x & 31;
    const int q    = lane & 3;
    const int g    = lane >> 2;
    const int half = (threadIdx.x >> 5) & 1;
    const int pair_in_blk = threadIdx.x >> 6;
    const int pair = blockIdx.x * 4 + pair_in_blk;
    const int t_base = pair * (WTILES * 16);
    if (t_base >= T) return;
    const int bar_id = 8 + pair_in_blk;

    // ---- B fragments: 16 coalesced LDG.64 from the precomputed buffer ----
    uint32_t bhi[8][2], blo[8][2];
#pragma unroll
    for (int j = 0; j < 8; ++j) {
        uint2 h = g_bHI[half][j][lane];
        uint2 l = g_bLO[half][j][lane];
        bhi[j][0] = h.x; bhi[j][1] = h.y;
        blo[j][0] = l.x; blo[j][1] = l.y;
    }

    const ulonglong2 zrow = make_ulonglong2(0ull, 0ull);

    // ---- prologue: load m-tile 0's rows ----
    int t0 = t_base;
    ulonglong2 r0 = zrow, r1 = zrow;
    {
        const int tr0 = t0 + g, tr1 = t0 + g + 8;
        if (tr0 < T) r0 = g_hist2[tr0];
        if (tr1 < T) r1 = g_hist2[tr1];
    }

#pragma unroll 1
    for (int mt = 0; mt < WTILES; ++mt) {
        const int tr0 = t0 + g;
        const int tr1 = t0 + g + 8;
        const bool ok0 = (tr0 < T);
        const bool ok1 = (tr1 < T);

        // ---- A fragments + lengths from packed rows ----
        uint32_t a0, a1, a2, a3;
        float len0, len1;
        row_frag(r0, q, a0, a2, len0);
        row_frag(r1, q, a1, a3, len1);
        const float s0 = __fdividef(1.0f, fmaxf(len0, 1.0f));
        const float s1 = __fdividef(1.0f, fmaxf(len1, 1.0f));

        // ---- pair barrier: both warps' loads of these rows are complete ----
        asm volatile("bar.sync %0, %1;" :: "r"(bar_id), "r"(64) : "memory");

        // ---- even warp clears the 16 consumed rows (16B each) ----
        if (half == 0 && lane < 16) {
            const int zr = t0 + lane;
            if (zr < T) g_hist2[zr] = zrow;
        }

        // ---- prefetch next m-tile's rows ----
        const int t0n = t0 + 16;
        if (mt + 1 < WTILES) {
            const int nr0 = t0n + g, nr1 = t0n + g + 8;
            r0 = zrow; r1 = zrow;
            if (nr0 < T) r0 = g_hist2[nr0];
            if (nr1 < T) r1 = g_hist2[nr1];
        }

        // ---- 4 tile-pairs: 4 MMAs each, one STG.128 per row ----
        float* po0 = out + (size_t)tr0 * 128 + 64 * half;
        float* po1 = out + (size_t)tr1 * 128 + 64 * half;
#pragma unroll
        for (int u = 0; u < 4; ++u) {
            float h0 = 0.f, h1 = 0.f, h2 = 0.f, h3 = 0.f;   // tile 2u hi
            float l0 = 0.f, l1 = 0.f, l2 = 0.f, l3 = 0.f;   // tile 2u lo
            float e0 = 0.f, e1 = 0.f, e2 = 0.f, e3 = 0.f;   // tile 2u+1 hi
            float m0 = 0.f, m1 = 0.f, m2 = 0.f, m3 = 0.f;   // tile 2u+1 lo
            mma_bf16(h0, h1, h2, h3, a0, a1, a2, a3, bhi[2*u][0],   bhi[2*u][1]);
            mma_bf16(l0, l1, l2, l3, a0, a1, a2, a3, blo[2*u][0],   blo[2*u][1]);
            mma_bf16(e0, e1, e2, e3, a0, a1, a2, a3, bhi[2*u+1][0], bhi[2*u+1][1]);
            mma_bf16(m0, m1, m2, m3, a0, a1, a2, a3, blo[2*u+1][0], blo[2*u+1][1]);
            if (ok0) *reinterpret_cast<float4*>(po0 + 16 * u + 4 * q) =
                make_float4((h0 + l0) * s0, (h1 + l1) * s0,
                            (e0 + m0) * s0, (e1 + m1) * s0);
            if (ok1) *reinterpret_cast<float4*>(po1 + 16 * u + 4 * q) =
                make_float4((h2 + l2) * s1, (h3 + l3) * s1,
                            (e2 + m2) * s1, (e3 + m3) * s1);
        }

        t0 = t0n;
    }
}

// ---------------------------------------------------------------------------
extern "C" void kernel_launch(void* const* d_in, const int* in_sizes, int n_in,
                              void* d_out, int out_size) {
    const float* char_emb     = (const float*)d_in[0];
    const int*   char_indices = (const int*)d_in[1];
    const int*   segment_ids  = (const int*)d_in[2];
    float*       out          = (float*)d_out;

    int N = in_sizes[1];          // total chars
    int T = out_size / 128;       // segments (d_model = 128)

    {   // histogram + B-fragment precompute: 8 chars/thread
        int nq8 = N >> 3;
        int threads = 256;
        int work = nq8 + 1;
        hist_kernel<<<(work + threads - 1) / threads, threads>>>(
            (const int4*)segment_ids, (const int4*)char_indices,
            segment_ids, char_indices, char_emb, nq8, N);
    }
    {   // HMMA GEMM: 8 warps = 4 warp-pairs per block, 32 segs per pair
        int segs_per_block = 4 * WTILES * 16;   // 128
        int blocks = (T + segs_per_block - 1) / segs_per_block;
        mma_kernel<<<blocks, 256>>>(out, T);
    }
}